// round 11
// baseline (speedup 1.0000x reference)
#include <cuda_runtime.h>
#include <cuda_fp16.h>
#include <cstdint>

#define V_   45
#define H_   1500
#define H2_  3000
#define G4_  6000   // 4*H
#define SW_  50
#define SD_  10
#define HP_  1536   // H padded
#define H2P_ 3072
#define NSMALL_ 98  // 3 ctrl + 50 si + 45 dec
#define TPB_ 768
#define NWARP_ 24

// ---------------- persistent device scratch ----------------
__device__ float g_EV[2 * V_ * G4_];                  // [dir][v][row]
__device__ float g_WSTT[2 * G4_ * SW_];               // [(d*6000 + grow)*50 + k]
__device__ __align__(16) float g_Whh[2 * G4_ * HP_];  // fp32 padded rows (L2-resident)
__device__ __align__(16) __half g_Wsm[NSMALL_ * H2P_];
__device__ __align__(16) float g_h[H2P_];
__device__ float g_stack[2][SD_ * SW_];
__device__ float g_ctrl_raw[3];
__device__ float g_si_raw[SW_];
__device__ volatile unsigned g_arr[256];
__device__ volatile unsigned g_gen;
__device__ volatile unsigned g_cs_arr[64];

// ---------------- grid barrier: 2-hop, hub block ----------------
__device__ __forceinline__ void gsync(unsigned gen, int nb, int hub) {
    __syncthreads();
    if (threadIdx.x == 0) { __threadfence(); g_arr[blockIdx.x] = gen; }
    if ((int)blockIdx.x == hub) {
        if (threadIdx.x < nb) {
            while (g_arr[threadIdx.x] < gen) { __nanosleep(16); }
        }
        __syncthreads();
        if (threadIdx.x == 0) g_gen = gen;
    } else {
        if (threadIdx.x == 0) {
            while (g_gen < gen) { __nanosleep(16); }
        }
        __syncthreads();
    }
    __syncthreads();
}

// ---------------- fused misc prep ----------------
#define WSTT_N (2 * G4_ * SW_)          // 600000
#define WSM_N  (NSMALL_ * H2P_)         // 301056
__global__ void prep_misc(const float* __restrict__ h0, const float* __restrict__ st0,
                          const float* __restrict__ Wih_f, const float* __restrict__ Wih_b,
                          const float* __restrict__ Wc, const float* __restrict__ Ws,
                          const float* __restrict__ Wd) {
    int idx = blockIdx.x * blockDim.x + threadIdx.x;
    if (idx < WSTT_N) {
        int gr2 = idx / SW_;
        int k = idx - gr2 * SW_;
        int d = gr2 / G4_;
        int r = gr2 - d * G4_;
        const float* W = d ? Wih_b : Wih_f;
        g_WSTT[idx] = W[(size_t)r * (H_ + SW_) + H_ + k];
        return;
    }
    int j = idx - WSTT_N;
    if (j < WSM_N) {
        int row = j / H2P_;
        int jj = j - row * H2P_;
        int d = jj >= HP_;
        int c = jj - d * HP_;
        float v = 0.f;
        if (c < H_) {
            int col = d * H_ + c;
            const float* src; int r;
            if (row < 3)       { src = Wc; r = row; }
            else if (row < 53) { src = Ws; r = row - 3; }
            else               { src = Wd; r = row - 53; }
            v = src[(size_t)r * H2_ + col];
        }
        g_Wsm[j] = __float2half(v);
        return;
    }
    int m = j - WSM_N;
    if (m < H2P_) {
        int d = m >= HP_;
        int i = m - d * HP_;
        g_h[m] = (i < H_) ? h0[d * H_ + i] : 0.f;
    } else if (m < H2P_ + SD_ * SW_) {
        g_stack[0][m - H2P_] = st0[m - H2P_];
    } else if (m < H2P_ + SD_ * SW_ + 256) {
        g_arr[m - H2P_ - SD_ * SW_] = 0u;
    } else if (m < H2P_ + SD_ * SW_ + 256 + 64) {
        g_cs_arr[m - H2P_ - SD_ * SW_ - 256] = 0u;
    } else if (m == H2P_ + SD_ * SW_ + 256 + 64) {
        g_gen = 0u;
    }
}
#define MISC_N (WSTT_N + WSM_N + H2P_ + SD_ * SW_ + 256 + 65)

__global__ void conv_whh(const float* __restrict__ Wf, const float* __restrict__ Wb) {
    int idx = blockIdx.x * blockDim.x + threadIdx.x;
    if (idx >= 2 * G4_ * HP_) return;
    int d = idx / (G4_ * HP_);
    int rem = idx - d * (G4_ * HP_);
    int r = rem / HP_;
    int k = rem - r * HP_;
    const float* W = d ? Wb : Wf;
    g_Whh[idx] = (k < H_) ? W[(size_t)r * H_ + k] : 0.f;
}

__global__ void __launch_bounds__(256) prep_ev(
    const float* __restrict__ Wih_f, const float* __restrict__ Wih_b,
    const float* __restrict__ bih_f, const float* __restrict__ bhh_f,
    const float* __restrict__ bih_b, const float* __restrict__ bhh_b,
    const float* __restrict__ emb) {
    __shared__ float As[64][17];
    __shared__ float Bs[16][49];
    const int dir = blockIdx.y;
    const float* Wih = dir ? Wih_b : Wih_f;
    const float* bih = dir ? bih_b : bih_f;
    const float* bhh = dir ? bhh_b : bhh_f;
    const int r0 = blockIdx.x * 64;
    const int tid = threadIdx.x;
    const int ty = tid >> 4;
    const int tx = tid & 15;
    float acc[4][3] = {};
    for (int k0 = 0; k0 < H_; k0 += 16) {
        #pragma unroll
        for (int j = 0; j < 4; ++j) {
            int li = tid + j * 256;
            int row = li >> 4, kk = li & 15;
            int gr = r0 + row, gk = k0 + kk;
            As[row][kk] = (gr < G4_ && gk < H_) ? Wih[(size_t)gr * (H_ + SW_) + gk] : 0.f;
        }
        #pragma unroll
        for (int j = 0; j < 3; ++j) {
            int li = tid + j * 256;
            int v = li >> 4, kk = li & 15;
            int gk = k0 + kk;
            Bs[kk][v] = (v < V_ && gk < H_) ? emb[(size_t)v * H_ + gk] : 0.f;
        }
        __syncthreads();
        #pragma unroll
        for (int kk = 0; kk < 16; ++kk) {
            float a0 = As[ty * 4 + 0][kk], a1 = As[ty * 4 + 1][kk];
            float a2 = As[ty * 4 + 2][kk], a3 = As[ty * 4 + 3][kk];
            float b0 = Bs[kk][tx * 3 + 0], b1 = Bs[kk][tx * 3 + 1], b2 = Bs[kk][tx * 3 + 2];
            acc[0][0] = fmaf(a0, b0, acc[0][0]); acc[0][1] = fmaf(a0, b1, acc[0][1]); acc[0][2] = fmaf(a0, b2, acc[0][2]);
            acc[1][0] = fmaf(a1, b0, acc[1][0]); acc[1][1] = fmaf(a1, b1, acc[1][1]); acc[1][2] = fmaf(a1, b2, acc[1][2]);
            acc[2][0] = fmaf(a2, b0, acc[2][0]); acc[2][1] = fmaf(a2, b1, acc[2][1]); acc[2][2] = fmaf(a2, b2, acc[2][2]);
            acc[3][0] = fmaf(a3, b0, acc[3][0]); acc[3][1] = fmaf(a3, b1, acc[3][1]); acc[3][2] = fmaf(a3, b2, acc[3][2]);
        }
        __syncthreads();
    }
    #pragma unroll
    for (int i = 0; i < 4; ++i) {
        int r = r0 + ty * 4 + i;
        if (r >= G4_) continue;
        float bb = bih[r] + bhh[r];
        #pragma unroll
        for (int j = 0; j < 3; ++j) {
            int v = tx * 3 + j;
            if (v < V_) g_EV[((size_t)(dir * V_ + v)) * G4_ + r] = acc[i][j] + bb;
        }
    }
}

// dual-accumulator fp16x8 dot (small rows only)
__device__ __forceinline__ void fma8d(float& a, float& b, uint4 u, float4 hA, float4 hB) {
    float2 f0 = __half22float2(*reinterpret_cast<__half2*>(&u.x));
    float2 f1 = __half22float2(*reinterpret_cast<__half2*>(&u.y));
    float2 f2 = __half22float2(*reinterpret_cast<__half2*>(&u.z));
    float2 f3 = __half22float2(*reinterpret_cast<__half2*>(&u.w));
    a = fmaf(f0.x, hA.x, a); a = fmaf(f0.y, hA.y, a);
    a = fmaf(f1.x, hA.z, a); a = fmaf(f1.y, hA.w, a);
    b = fmaf(f2.x, hB.x, b); b = fmaf(f2.y, hB.y, b);
    b = fmaf(f3.x, hB.z, b); b = fmaf(f3.y, hB.w, b);
}

// NR rows, single k-pass, fp32 weights, dual accumulators, all LDGs in flight
template<int NR>
__device__ __forceinline__ void row_dots(const float4* const* wp, const float4* hb,
                                         int lane, float* accOut) {
    float aA[NR], aB[NR];
    #pragma unroll
    for (int r = 0; r < NR; ++r) { aA[r] = 0.f; aB[r] = 0.f; }
    #pragma unroll
    for (int it = 0; it < 6; ++it) {
        const int o = it * 32 + lane;
        const float4 hA = hb[2 * o];
        const float4 hB = hb[2 * o + 1];
        #pragma unroll
        for (int r = 0; r < NR; ++r) {
            const float4 w0 = wp[r][2 * o];
            const float4 w1 = wp[r][2 * o + 1];
            aA[r] = fmaf(w0.x, hA.x, aA[r]); aA[r] = fmaf(w0.y, hA.y, aA[r]);
            aA[r] = fmaf(w0.z, hA.z, aA[r]); aA[r] = fmaf(w0.w, hA.w, aA[r]);
            aB[r] = fmaf(w1.x, hB.x, aB[r]); aB[r] = fmaf(w1.y, hB.y, aB[r]);
            aB[r] = fmaf(w1.z, hB.z, aB[r]); aB[r] = fmaf(w1.w, hB.w, aB[r]);
        }
    }
    #pragma unroll
    for (int r = 0; r < NR; ++r) accOut[r] = aA[r] + aB[r];
}

// full-length (2H) small-row dot over sh_h (fp16 weights)
__device__ __forceinline__ float small_dot(int sid, const float* sh_h, int lane) {
    const uint4* W = (const uint4*)(g_Wsm + (size_t)sid * H2P_);
    const float4* s4 = (const float4*)sh_h;
    float a = 0.f, b = 0.f;
    #pragma unroll
    for (int it = 0; it < 12; ++it) {
        const int o = lane + it * 32;
        uint4 u = W[o];
        fma8d(a, b, u, s4[2 * o], s4[2 * o + 1]);
    }
    float acc = a + b;
    #pragma unroll
    for (int o = 16; o; o >>= 1) acc += __shfl_xor_sync(0xffffffffu, acc, o);
    return acc;
}

// ---------------- persistent main kernel ----------------
__global__ void __launch_bounds__(TPB_, 1) rnn_main(
    const int* __restrict__ tokens, const float* __restrict__ cell0,
    const float* __restrict__ bctrl, const float* __restrict__ bsi,
    const float* __restrict__ bdec,
    float* __restrict__ out, int T) {
    __shared__ __align__(16) float sh_h[H2P_];
    __shared__ float s_gate[80];
    __shared__ float s_stop[SW_];

    const int bid  = blockIdx.x;
    const int tid  = threadIdx.x;
    const int lane = tid & 31;
    const int warp = tid >> 5;
    const int NB   = gridDim.x;
    const int hub  = NB - 1;

    // block-owned contiguous unit range
    const int ubase = H2_ / NB, urem = H2_ % NB;
    const int un = ubase + (bid < urem ? 1 : 0);
    const int u0 = bid * ubase + (bid < urem ? bid : urem);
    const int nrows = 4 * un;
    const bool has_small = (bid < NSMALL_);
    const int dstride = has_small ? (NWARP_ - 1) : NWARP_;
    const bool is_smallw = (has_small && warp == NWARP_ - 1);

    // ---- static per-warp row list (fixed across steps), max 4 rows ----
    int nr = 0;
    int rowrl[4], rowd[4], rowg[4];
    const float4* wp[4];
    if (!is_smallw) {
        for (int rl = warp; rl < nrows && nr < 4; rl += dstride) {
            const int ul = rl >> 2, g = rl & 3;
            const int uu = u0 + ul;
            const int d = (uu >= H_);
            const int i = uu - d * H_;
            const int grow = g * H_ + i;
            rowrl[nr] = rl; rowd[nr] = d; rowg[nr] = grow;
            wp[nr] = (const float4*)(g_Whh + ((size_t)(d * G4_ + grow)) * HP_);
            ++nr;
        }
    }
    bool dirsame = true;
    for (int ri = 1; ri < nr; ++ri) if (rowd[ri] != rowd[0]) dirsame = false;

    // persistent cell state in registers (lane0's copy authoritative)
    float creg0 = 0.f;
    int myu0 = -1;
    if (warp < un) { myu0 = u0 + warp; creg0 = cell0[myu0]; }

    unsigned gen = 0;

    for (int t = 0; t <= T; ++t) {
        // ---- stage h ----
        __syncthreads();
        ((float4*)sh_h)[tid] = __ldcg((const float4*)g_h + tid);   // H2P_/4 == TPB_
        __syncthreads();

        if (t == T) {   // final logits row for step T-1
            if (is_smallw && bid >= 53) {
                float acc = small_dot(bid, sh_h, lane);
                if (lane == 0) out[(size_t)(T - 1) * V_ + (bid - 53)] = acc + bdec[bid - 53];
            }
            break;
        }
        const int tok = tokens[t];

        // ---- small rows (ctrl/si publish flags; dec straight to out) ----
        if (is_smallw) {
            const int sid = bid;
            if (sid < 53) {
                float acc = small_dot(sid, sh_h, lane);
                if (lane == 0) {
                    if (sid < 3) g_ctrl_raw[sid] = acc + bctrl[sid];
                    else         g_si_raw[sid - 3] = acc + bsi[sid - 3];
                    __threadfence();
                    g_cs_arr[sid] = (unsigned)(t + 1);
                }
            } else if (t >= 1) {
                float acc = small_dot(sid, sh_h, lane);
                if (lane == 0) out[(size_t)(t - 1) * V_ + (sid - 53)] = acc + bdec[sid - 53];
            }
        } else if (nr > 0) {
            float acc[4] = {0.f, 0.f, 0.f, 0.f};
            if (dirsame) {
                const float4* hb = (const float4*)(sh_h + rowd[0] * HP_);
                switch (nr) {
                    case 4: row_dots<4>(wp, hb, lane, acc); break;
                    case 3: row_dots<3>(wp, hb, lane, acc); break;
                    case 2: row_dots<2>(wp, hb, lane, acc); break;
                    default: row_dots<1>(wp, hb, lane, acc); break;
                }
            } else {
                for (int ri = 0; ri < nr; ++ri) {
                    const float4* hb = (const float4*)(sh_h + rowd[ri] * HP_);
                    row_dots<1>(wp + ri, hb, lane, acc + ri);
                }
            }
            #pragma unroll
            for (int ri = 0; ri < 4; ++ri) {
                if (ri < nr) {
                    float a = acc[ri];
                    #pragma unroll
                    for (int o = 16; o; o >>= 1) a += __shfl_xor_sync(0xffffffffu, a, o);
                    if (lane == 0) {
                        const float ev = __ldg(&g_EV[((size_t)(rowd[ri] * V_ + tok)) * G4_ + rowg[ri]]);
                        s_gate[rowrl[ri]] = a + ev;
                    }
                }
            }
        }

        // ---- wait for ctrl/si: warp 0 polls flag array (batched, no atomics) ----
        if (warp == 0) {
            const int s0 = lane;
            const int s1 = (lane + 32 < 53) ? lane + 32 : 0;
            for (;;) {
                unsigned v0 = g_cs_arr[s0 < 53 ? s0 : 0];
                unsigned v1 = g_cs_arr[s1];
                if (__all_sync(0xffffffffu, v0 >= (unsigned)(t + 1) && v1 >= (unsigned)(t + 1))) break;
                __nanosleep(16);
            }
        }
        __syncthreads();

        // ---- s_stop (+ stack rows on hub block) ----
        const float* stOld = g_stack[t & 1];
        float* stNew = g_stack[(t + 1) & 1];
        if (tid < SW_ + 450) {
            const float c0r = __ldcg(&g_ctrl_raw[0]);
            const float c1r = __ldcg(&g_ctrl_raw[1]);
            const float c2r = __ldcg(&g_ctrl_raw[2]);
            const float m = fmaxf(c0r, fmaxf(c1r, c2r));
            const float e0 = __expf(c0r - m), e1 = __expf(c1r - m), e2 = __expf(c2r - m);
            const float inv = 1.f / (e0 + e1 + e2);
            const float c0 = e0 * inv, c1 = e1 * inv, c2 = e2 * inv;
            if (tid < SW_) {
                const float sv = tanhf(__ldcg(&g_si_raw[tid]));
                const float sp = c2 * __ldcg(&stOld[tid]) + c0 * sv + c1 * __ldcg(&stOld[SW_ + tid]);
                s_stop[tid] = sp;
                if (bid == hub) stNew[tid] = sp;
            } else if (bid == hub) {
                const int idx = tid - SW_;
                const int dd = 1 + idx / SW_;
                const int k = idx - (dd - 1) * SW_;
                const float up = __ldcg(&stOld[(dd - 1) * SW_ + k]);
                const float dn = (dd < SD_ - 1) ? __ldcg(&stOld[(dd + 1) * SW_ + k]) : 0.f;
                stNew[dd * SW_ + k] = c2 * __ldcg(&stOld[dd * SW_ + k]) + c0 * up + c1 * dn;
            }
        }
        __syncthreads();

        // ---- pointwise LSTM update (warp per owned unit) ----
        if (myu0 >= 0) {
            const int u = myu0;
            const int ul = u - u0;
            const int d = (u >= H_);
            const int i = u - d * H_;
            const int g8 = lane >> 3;
            const int k0 = lane & 7;
            const float* wst = g_WSTT + ((size_t)(d * G4_ + g8 * H_ + i)) * SW_;
            float sp = 0.f;
            #pragma unroll
            for (int j = 0; j < 7; ++j) {
                const int k = k0 + 8 * j;
                if (k < SW_) sp = fmaf(wst[k], s_stop[k], sp);
            }
            sp += __shfl_xor_sync(0xffffffffu, sp, 1);
            sp += __shfl_xor_sync(0xffffffffu, sp, 2);
            sp += __shfl_xor_sync(0xffffffffu, sp, 4);
            const float tot = s_gate[4 * ul + g8] + sp;
            const float act = (g8 == 2) ? tanhf(tot) : (1.f / (1.f + __expf(-tot)));
            const float is = __shfl_sync(0xffffffffu, act, 0);
            const float fs = __shfl_sync(0xffffffffu, act, 8);
            const float gt = __shfl_sync(0xffffffffu, act, 16);
            const float os = __shfl_sync(0xffffffffu, act, 24);
            if (lane == 0) {
                const float cc = fs * creg0 + is * gt;
                creg0 = cc;
                g_h[d * HP_ + i] = os * tanhf(cc);
            }
        }

        gsync(++gen, NB, hub);
    }
}

// ---------------- launch ----------------
extern "C" void kernel_launch(void* const* d_in, const int* in_sizes, int n_in,
                              void* d_out, int out_size) {
    const int*   tokens  = (const int*)  d_in[0];
    const float* hidden0 = (const float*)d_in[1];
    const float* cell0   = (const float*)d_in[2];
    const float* stack0  = (const float*)d_in[3];
    const float* emb     = (const float*)d_in[4];
    const float* Wctrl   = (const float*)d_in[5];
    const float* bctrl   = (const float*)d_in[6];
    const float* Wsi     = (const float*)d_in[7];
    const float* bsi     = (const float*)d_in[8];
    const float* Wih_f   = (const float*)d_in[9];
    const float* Whh_f   = (const float*)d_in[10];
    const float* bih_f   = (const float*)d_in[11];
    const float* bhh_f   = (const float*)d_in[12];
    const float* Wih_b   = (const float*)d_in[13];
    const float* Whh_b   = (const float*)d_in[14];
    const float* bih_b   = (const float*)d_in[15];
    const float* bhh_b   = (const float*)d_in[16];
    const float* Wdec    = (const float*)d_in[17];
    const float* bdec    = (const float*)d_in[18];
    float* out = (float*)d_out;
    const int T = in_sizes[0];

    int dev = 0;
    cudaGetDevice(&dev);
    int nsm = 0;
    cudaDeviceGetAttribute(&nsm, cudaDevAttrMultiProcessorCount, dev);
    if (nsm <= 0) nsm = 148;
    if (nsm > 256) nsm = 256;

    prep_misc<<<(MISC_N + 255) / 256, 256>>>(hidden0, stack0, Wih_f, Wih_b, Wctrl, Wsi, Wdec);
    conv_whh<<<(2 * G4_ * HP_ + 255) / 256, 256>>>(Whh_f, Whh_b);
    dim3 gev((G4_ + 63) / 64, 2);
    prep_ev<<<gev, 256>>>(Wih_f, Wih_b, bih_f, bhh_f, bih_b, bhh_b, emb);
    rnn_main<<<nsm, TPB_>>>(tokens, cell0, bctrl, bsi, bdec, out, T);
}

// round 16
// speedup vs baseline: 1.2744x; 1.2744x over previous
#include <cuda_runtime.h>
#include <cuda_fp16.h>
#include <cstdint>

#define V_   45
#define H_   1500
#define H2_  3000
#define G4_  6000   // 4*H
#define SW_  50
#define SD_  10
#define HP_  1536   // H padded
#define H2P_ 3072
#define NSMALL_ 98  // 3 ctrl + 50 si + 45 dec
#define TPB_ 768
#define NWARP_ 24

// ---------------- persistent device scratch ----------------
__device__ float g_EV[2 * V_ * G4_];                  // [dir][v][row]
__device__ float g_WSTT[2 * G4_ * SW_];               // [(d*6000 + grow)*50 + k]
__device__ __align__(16) __half g_Whh[2 * G4_ * HP_]; // fp16 (L1-resident per SM)
__device__ __align__(16) __half g_Wsm[NSMALL_ * H2P_];
__device__ __align__(16) float g_h[2][H2P_];          // double-buffered hidden
__device__ float g_stack[2][SD_ * SW_];
__device__ float g_ctrl_raw[3];
__device__ float g_si_raw[SW_];
__device__ volatile unsigned g_arr[256];              // per-block h-ready flags
__device__ volatile unsigned g_cs_arr[64];            // per-small-row ready flags

// ---------------- fused misc prep ----------------
#define WSTT_N (2 * G4_ * SW_)          // 600000
#define WSM_N  (NSMALL_ * H2P_)         // 301056
__global__ void prep_misc(const float* __restrict__ h0, const float* __restrict__ st0,
                          const float* __restrict__ Wih_f, const float* __restrict__ Wih_b,
                          const float* __restrict__ Wc, const float* __restrict__ Ws,
                          const float* __restrict__ Wd) {
    int idx = blockIdx.x * blockDim.x + threadIdx.x;
    if (idx < WSTT_N) {
        int gr2 = idx / SW_;
        int k = idx - gr2 * SW_;
        int d = gr2 / G4_;
        int r = gr2 - d * G4_;
        const float* W = d ? Wih_b : Wih_f;
        g_WSTT[idx] = W[(size_t)r * (H_ + SW_) + H_ + k];
        return;
    }
    int j = idx - WSTT_N;
    if (j < WSM_N) {
        int row = j / H2P_;
        int jj = j - row * H2P_;
        int d = jj >= HP_;
        int c = jj - d * HP_;
        float v = 0.f;
        if (c < H_) {
            int col = d * H_ + c;
            const float* src; int r;
            if (row < 3)       { src = Wc; r = row; }
            else if (row < 53) { src = Ws; r = row - 3; }
            else               { src = Wd; r = row - 53; }
            v = src[(size_t)r * H2_ + col];
        }
        g_Wsm[j] = __float2half(v);
        return;
    }
    int m = j - WSM_N;
    if (m < H2P_) {
        int d = m >= HP_;
        int i = m - d * HP_;
        g_h[0][m] = (i < H_) ? h0[d * H_ + i] : 0.f;
    } else if (m < H2P_ + SD_ * SW_) {
        g_stack[0][m - H2P_] = st0[m - H2P_];
    } else if (m < H2P_ + SD_ * SW_ + 256) {
        g_arr[m - H2P_ - SD_ * SW_] = 0u;
    } else if (m < H2P_ + SD_ * SW_ + 256 + 64) {
        g_cs_arr[m - H2P_ - SD_ * SW_ - 256] = 0u;
    }
}
#define MISC_N (WSTT_N + WSM_N + H2P_ + SD_ * SW_ + 256 + 64)

__global__ void conv_whh(const float* __restrict__ Wf, const float* __restrict__ Wb) {
    int idx = blockIdx.x * blockDim.x + threadIdx.x;
    if (idx >= 2 * G4_ * HP_) return;
    int d = idx / (G4_ * HP_);
    int rem = idx - d * (G4_ * HP_);
    int r = rem / HP_;
    int k = rem - r * HP_;
    const float* W = d ? Wb : Wf;
    float v = (k < H_) ? W[(size_t)r * H_ + k] : 0.f;
    g_Whh[idx] = __float2half(v);
}

__global__ void __launch_bounds__(256) prep_ev(
    const float* __restrict__ Wih_f, const float* __restrict__ Wih_b,
    const float* __restrict__ bih_f, const float* __restrict__ bhh_f,
    const float* __restrict__ bih_b, const float* __restrict__ bhh_b,
    const float* __restrict__ emb) {
    __shared__ float As[64][17];
    __shared__ float Bs[16][49];
    const int dir = blockIdx.y;
    const float* Wih = dir ? Wih_b : Wih_f;
    const float* bih = dir ? bih_b : bih_f;
    const float* bhh = dir ? bhh_b : bhh_f;
    const int r0 = blockIdx.x * 64;
    const int tid = threadIdx.x;
    const int ty = tid >> 4;
    const int tx = tid & 15;
    float acc[4][3] = {};
    for (int k0 = 0; k0 < H_; k0 += 16) {
        #pragma unroll
        for (int j = 0; j < 4; ++j) {
            int li = tid + j * 256;
            int row = li >> 4, kk = li & 15;
            int gr = r0 + row, gk = k0 + kk;
            As[row][kk] = (gr < G4_ && gk < H_) ? Wih[(size_t)gr * (H_ + SW_) + gk] : 0.f;
        }
        #pragma unroll
        for (int j = 0; j < 3; ++j) {
            int li = tid + j * 256;
            int v = li >> 4, kk = li & 15;
            int gk = k0 + kk;
            Bs[kk][v] = (v < V_ && gk < H_) ? emb[(size_t)v * H_ + gk] : 0.f;
        }
        __syncthreads();
        #pragma unroll
        for (int kk = 0; kk < 16; ++kk) {
            float a0 = As[ty * 4 + 0][kk], a1 = As[ty * 4 + 1][kk];
            float a2 = As[ty * 4 + 2][kk], a3 = As[ty * 4 + 3][kk];
            float b0 = Bs[kk][tx * 3 + 0], b1 = Bs[kk][tx * 3 + 1], b2 = Bs[kk][tx * 3 + 2];
            acc[0][0] = fmaf(a0, b0, acc[0][0]); acc[0][1] = fmaf(a0, b1, acc[0][1]); acc[0][2] = fmaf(a0, b2, acc[0][2]);
            acc[1][0] = fmaf(a1, b0, acc[1][0]); acc[1][1] = fmaf(a1, b1, acc[1][1]); acc[1][2] = fmaf(a1, b2, acc[1][2]);
            acc[2][0] = fmaf(a2, b0, acc[2][0]); acc[2][1] = fmaf(a2, b1, acc[2][1]); acc[2][2] = fmaf(a2, b2, acc[2][2]);
            acc[3][0] = fmaf(a3, b0, acc[3][0]); acc[3][1] = fmaf(a3, b1, acc[3][1]); acc[3][2] = fmaf(a3, b2, acc[3][2]);
        }
        __syncthreads();
    }
    #pragma unroll
    for (int i = 0; i < 4; ++i) {
        int r = r0 + ty * 4 + i;
        if (r >= G4_) continue;
        float bb = bih[r] + bhh[r];
        #pragma unroll
        for (int j = 0; j < 3; ++j) {
            int v = tx * 3 + j;
            if (v < V_) g_EV[((size_t)(dir * V_ + v)) * G4_ + r] = acc[i][j] + bb;
        }
    }
}

// dual-accumulator fp16x8 dot
__device__ __forceinline__ void fma8d(float& a, float& b, uint4 u, float4 hA, float4 hB) {
    float2 f0 = __half22float2(*reinterpret_cast<__half2*>(&u.x));
    float2 f1 = __half22float2(*reinterpret_cast<__half2*>(&u.y));
    float2 f2 = __half22float2(*reinterpret_cast<__half2*>(&u.z));
    float2 f3 = __half22float2(*reinterpret_cast<__half2*>(&u.w));
    a = fmaf(f0.x, hA.x, a); a = fmaf(f0.y, hA.y, a);
    a = fmaf(f1.x, hA.z, a); a = fmaf(f1.y, hA.w, a);
    b = fmaf(f2.x, hB.x, b); b = fmaf(f2.y, hB.y, b);
    b = fmaf(f3.x, hB.z, b); b = fmaf(f3.y, hB.w, b);
}

// NR rows, single k-pass, all LDGs in flight per iteration
template<int NR>
__device__ __forceinline__ void row_dots(const uint4* const* wp, const float4* hb,
                                         int lane, float* accOut) {
    float aA[NR], aB[NR];
    #pragma unroll
    for (int r = 0; r < NR; ++r) { aA[r] = 0.f; aB[r] = 0.f; }
    #pragma unroll
    for (int it = 0; it < 6; ++it) {
        const int o = it * 32 + lane;
        const float4 hA = hb[2 * o];
        const float4 hB = hb[2 * o + 1];
        #pragma unroll
        for (int r = 0; r < NR; ++r) {
            uint4 u = wp[r][o];
            fma8d(aA[r], aB[r], u, hA, hB);
        }
    }
    #pragma unroll
    for (int r = 0; r < NR; ++r) accOut[r] = aA[r] + aB[r];
}

// full-length (2H) small-row dot over sh_h
__device__ __forceinline__ float small_dot(int sid, const float* sh_h, int lane) {
    const uint4* W = (const uint4*)(g_Wsm + (size_t)sid * H2P_);
    const float4* s4 = (const float4*)sh_h;
    float a = 0.f, b = 0.f;
    #pragma unroll
    for (int it = 0; it < 12; ++it) {
        const int o = lane + it * 32;
        uint4 u = W[o];
        fma8d(a, b, u, s4[2 * o], s4[2 * o + 1]);
    }
    float acc = a + b;
    #pragma unroll
    for (int o = 16; o; o >>= 1) acc += __shfl_xor_sync(0xffffffffu, acc, o);
    return acc;
}

// ---------------- persistent main kernel: NO grid barrier, flag-based flow ----------------
__global__ void __launch_bounds__(TPB_, 1) rnn_main(
    const int* __restrict__ tokens, const float* __restrict__ cell0,
    const float* __restrict__ bctrl, const float* __restrict__ bsi,
    const float* __restrict__ bdec,
    float* __restrict__ out, int T) {
    __shared__ __align__(16) float sh_h[H2P_];
    __shared__ float s_gate[80];
    __shared__ float s_stop[64];   // padded; [50..63] zeroed

    const int bid  = blockIdx.x;
    const int tid  = threadIdx.x;
    const int lane = tid & 31;
    const int warp = tid >> 5;
    const int NB   = gridDim.x;
    const int hub  = NB - 1;

    // block-owned contiguous unit range
    const int ubase = H2_ / NB, urem = H2_ % NB;
    const int un = ubase + (bid < urem ? 1 : 0);
    const int u0 = bid * ubase + (bid < urem ? bid : urem);
    const int nrows = 4 * un;
    const bool has_small = (bid < NSMALL_);
    const int dstride = has_small ? (NWARP_ - 1) : NWARP_;
    const bool is_smallw = (has_small && warp == NWARP_ - 1);

    // ---- static per-warp row list (fixed across steps), max 4 rows ----
    int nr = 0;
    int rowrl[4], rowd[4], rowg[4];
    const uint4* wp[4];
    if (!is_smallw) {
        for (int rl = warp; rl < nrows && nr < 4; rl += dstride) {
            const int ul = rl >> 2, g = rl & 3;
            const int uu = u0 + ul;
            const int d = (uu >= H_);
            const int i = uu - d * H_;
            const int grow = g * H_ + i;
            rowrl[nr] = rl; rowd[nr] = d; rowg[nr] = grow;
            wp[nr] = (const uint4*)(g_Whh + ((size_t)(d * G4_ + grow)) * HP_);
            ++nr;
        }
    }
    bool dirsame = true;
    for (int ri = 1; ri < nr; ++ri) if (rowd[ri] != rowd[0]) dirsame = false;

    // persistent cell state + hoisted static stack-projection weights
    float creg0 = 0.f;
    float wreg[7];
    int myu0 = -1;
    if (warp < un) {
        myu0 = u0 + warp;
        creg0 = cell0[myu0];
        const int d = (myu0 >= H_);
        const int i = myu0 - d * H_;
        const int g8 = lane >> 3, k0 = lane & 7;
        const float* wst = g_WSTT + ((size_t)(d * G4_ + g8 * H_ + i)) * SW_;
        #pragma unroll
        for (int j = 0; j < 7; ++j) {
            const int k = k0 + 8 * j;
            wreg[j] = (k < SW_) ? wst[k] : 0.f;
        }
    }
    if (tid >= SW_ && tid < 64) s_stop[tid] = 0.f;     // pad zero (never rewritten)

    for (int t = 0; t <= T; ++t) {
        // ---- wait for all blocks' h(t) flags, then stage h ----
        if (warp == 0) {
            for (;;) {
                bool ok = true;
                #pragma unroll
                for (int j = 0; j < 5; ++j) {
                    const int idx = lane + 32 * j;
                    if (idx < NB && g_arr[idx] < (unsigned)t) ok = false;
                }
                if (__all_sync(0xffffffffu, ok)) break;
                __nanosleep(16);
            }
        }
        __syncthreads();
        ((float4*)sh_h)[tid] = __ldcg((const float4*)g_h[t & 1] + tid);   // H2P_/4 == TPB_
        __syncthreads();

        if (t == T) {   // final logits row for step T-1
            if (is_smallw && bid >= 53) {
                float acc = small_dot(bid, sh_h, lane);
                if (lane == 0) out[(size_t)(T - 1) * V_ + (bid - 53)] = acc + bdec[bid - 53];
            }
            break;
        }
        const int tok = tokens[t];

        // ---- small rows (ctrl/si publish flags; dec straight to out) ----
        if (is_smallw) {
            const int sid = bid;
            if (sid < 53) {
                float acc = small_dot(sid, sh_h, lane);
                if (lane == 0) {
                    if (sid < 3) g_ctrl_raw[sid] = acc + bctrl[sid];
                    else         g_si_raw[sid - 3] = acc + bsi[sid - 3];
                    __threadfence();
                    g_cs_arr[sid] = (unsigned)(t + 1);
                }
            } else if (t >= 1) {
                float acc = small_dot(sid, sh_h, lane);
                if (lane == 0) out[(size_t)(t - 1) * V_ + (sid - 53)] = acc + bdec[sid - 53];
            }
        } else if (nr > 0) {
            float acc[4] = {0.f, 0.f, 0.f, 0.f};
            if (dirsame) {
                const float4* hb = (const float4*)(sh_h + rowd[0] * HP_);
                switch (nr) {
                    case 4: row_dots<4>(wp, hb, lane, acc); break;
                    case 3: row_dots<3>(wp, hb, lane, acc); break;
                    case 2: row_dots<2>(wp, hb, lane, acc); break;
                    default: row_dots<1>(wp, hb, lane, acc); break;
                }
            } else {
                for (int ri = 0; ri < nr; ++ri) {
                    const float4* hb = (const float4*)(sh_h + rowd[ri] * HP_);
                    row_dots<1>(wp + ri, hb, lane, acc + ri);
                }
            }
            #pragma unroll
            for (int ri = 0; ri < 4; ++ri) {
                if (ri < nr) {
                    float a = acc[ri];
                    #pragma unroll
                    for (int o = 16; o; o >>= 1) a += __shfl_xor_sync(0xffffffffu, a, o);
                    if (lane == 0) {
                        const float ev = __ldg(&g_EV[((size_t)(rowd[ri] * V_ + tok)) * G4_ + rowg[ri]]);
                        s_gate[rowrl[ri]] = a + ev;
                    }
                }
            }
        }

        // ---- wait for ctrl/si: warp 0 polls flag array ----
        if (warp == 0) {
            const int s0 = lane;
            const int s1 = (lane + 32 < 53) ? lane + 32 : 0;
            for (;;) {
                unsigned v0 = g_cs_arr[s0 < 53 ? s0 : 0];
                unsigned v1 = g_cs_arr[s1];
                if (__all_sync(0xffffffffu, v0 >= (unsigned)(t + 1) && v1 >= (unsigned)(t + 1))) break;
                __nanosleep(16);
            }
        }
        __syncthreads();

        // ---- s_stop (+ stack rows on hub block) ----
        const float* stOld = g_stack[t & 1];
        float* stNew = g_stack[(t + 1) & 1];
        if (tid < SW_ + 450) {
            const float c0r = __ldcg(&g_ctrl_raw[0]);
            const float c1r = __ldcg(&g_ctrl_raw[1]);
            const float c2r = __ldcg(&g_ctrl_raw[2]);
            const float m = fmaxf(c0r, fmaxf(c1r, c2r));
            const float e0 = __expf(c0r - m), e1 = __expf(c1r - m), e2 = __expf(c2r - m);
            const float inv = 1.f / (e0 + e1 + e2);
            const float c0 = e0 * inv, c1 = e1 * inv, c2 = e2 * inv;
            if (tid < SW_) {
                const float sv = tanhf(__ldcg(&g_si_raw[tid]));
                const float sp = c2 * __ldcg(&stOld[tid]) + c0 * sv + c1 * __ldcg(&stOld[SW_ + tid]);
                s_stop[tid] = sp;
                if (bid == hub) stNew[tid] = sp;
            } else if (bid == hub) {
                const int idx = tid - SW_;
                const int dd = 1 + idx / SW_;
                const int k = idx - (dd - 1) * SW_;
                const float up = __ldcg(&stOld[(dd - 1) * SW_ + k]);
                const float dn = (dd < SD_ - 1) ? __ldcg(&stOld[(dd + 1) * SW_ + k]) : 0.f;
                stNew[dd * SW_ + k] = c2 * __ldcg(&stOld[dd * SW_ + k]) + c0 * up + c1 * dn;
            }
        }
        __syncthreads();

        // ---- pointwise LSTM update (warp per owned unit; weights pre-hoisted) ----
        if (myu0 >= 0) {
            const int u = myu0;
            const int ul = u - u0;
            const int d = (u >= H_);
            const int i = u - d * H_;
            const int g8 = lane >> 3;
            const int k0 = lane & 7;
            float sp = 0.f;
            #pragma unroll
            for (int j = 0; j < 7; ++j) sp = fmaf(wreg[j], s_stop[k0 + 8 * j], sp);
            sp += __shfl_xor_sync(0xffffffffu, sp, 1);
            sp += __shfl_xor_sync(0xffffffffu, sp, 2);
            sp += __shfl_xor_sync(0xffffffffu, sp, 4);
            const float tot = s_gate[4 * ul + g8] + sp;
            const float act = (g8 == 2) ? tanhf(tot) : (1.f / (1.f + __expf(-tot)));
            const float is = __shfl_sync(0xffffffffu, act, 0);
            const float fs = __shfl_sync(0xffffffffu, act, 8);
            const float gt = __shfl_sync(0xffffffffu, act, 16);
            const float os = __shfl_sync(0xffffffffu, act, 24);
            if (lane == 0) {
                const float cc = fs * creg0 + is * gt;
                creg0 = cc;
                g_h[(t + 1) & 1][d * HP_ + i] = os * tanhf(cc);
            }
        }

        // ---- publish h(t+1) readiness (replaces the grid barrier) ----
        __syncthreads();
        if (tid == 0) { __threadfence(); g_arr[bid] = (unsigned)(t + 1); }
    }
}

// ---------------- launch ----------------
extern "C" void kernel_launch(void* const* d_in, const int* in_sizes, int n_in,
                              void* d_out, int out_size) {
    const int*   tokens  = (const int*)  d_in[0];
    const float* hidden0 = (const float*)d_in[1];
    const float* cell0   = (const float*)d_in[2];
    const float* stack0  = (const float*)d_in[3];
    const float* emb     = (const float*)d_in[4];
    const float* Wctrl   = (const float*)d_in[5];
    const float* bctrl   = (const float*)d_in[6];
    const float* Wsi     = (const float*)d_in[7];
    const float* bsi     = (const float*)d_in[8];
    const float* Wih_f   = (const float*)d_in[9];
    const float* Whh_f   = (const float*)d_in[10];
    const float* bih_f   = (const float*)d_in[11];
    const float* bhh_f   = (const float*)d_in[12];
    const float* Wih_b   = (const float*)d_in[13];
    const float* Whh_b   = (const float*)d_in[14];
    const float* bih_b   = (const float*)d_in[15];
    const float* bhh_b   = (const float*)d_in[16];
    const float* Wdec    = (const float*)d_in[17];
    const float* bdec    = (const float*)d_in[18];
    float* out = (float*)d_out;
    const int T = in_sizes[0];

    int dev = 0;
    cudaGetDevice(&dev);
    int nsm = 0;
    cudaDeviceGetAttribute(&nsm, cudaDevAttrMultiProcessorCount, dev);
    if (nsm <= 0) nsm = 148;
    if (nsm > 160) nsm = 160;   // flags poll covers 5*32=160

    prep_misc<<<(MISC_N + 255) / 256, 256>>>(hidden0, stack0, Wih_f, Wih_b, Wctrl, Wsi, Wdec);
    conv_whh<<<(2 * G4_ * HP_ + 255) / 256, 256>>>(Whh_f, Whh_b);
    dim3 gev((G4_ + 63) / 64, 2);
    prep_ev<<<gev, 256>>>(Wih_f, Wih_b, bih_f, bhh_f, bih_b, bhh_b, emb);
    rnn_main<<<nsm, TPB_>>>(tokens, cell0, bctrl, bsi, bdec, out, T);
}

// round 17
// speedup vs baseline: 1.4276x; 1.1202x over previous
#include <cuda_runtime.h>
#include <cuda_fp16.h>
#include <cstdint>

#define V_   45
#define H_   1500
#define H2_  3000
#define G4_  6000   // 4*H
#define SW_  50
#define SD_  10
#define HP_  1536   // H padded
#define H2P_ 3072
#define NSMALL_ 98  // 3 ctrl + 50 si + 45 dec
#define TPB_ 768
#define NWARP_ 24
#define NCS_ 53     // 3 ctrl + 50 si

// ---------------- persistent device scratch ----------------
__device__ float g_EV[2 * V_ * G4_];                  // [dir][v][row]
__device__ float g_WSTT[2 * G4_ * SW_];               // [(d*6000 + grow)*50 + k]
__device__ __align__(16) __half g_Whh[2 * G4_ * HP_]; // fp16 (L1-resident per SM)
__device__ __align__(16) __half g_Wsm[NSMALL_ * H2P_];
__device__ float g_WsmT[H2_ * 56];                    // [col][row] fp32, rows 0..52 (ctrl|si)
__device__ __align__(16) float g_h[2][H2P_];          // double-buffered hidden
__device__ float g_stack[2][SD_ * SW_];
__device__ float g_cs_buf[3][64];                     // rotating ctrl/si accumulators
__device__ volatile unsigned g_arr[256];
__device__ volatile unsigned g_gen;

// ---------------- fused misc prep ----------------
#define WSTT_N (2 * G4_ * SW_)          // 600000
#define WSM_N  (NSMALL_ * H2P_)         // 301056
#define WSMT_N (NCS_ * H2_)             // 159000
__global__ void prep_misc(const float* __restrict__ h0, const float* __restrict__ st0,
                          const float* __restrict__ Wih_f, const float* __restrict__ Wih_b,
                          const float* __restrict__ Wc, const float* __restrict__ Ws,
                          const float* __restrict__ Wd,
                          const float* __restrict__ bc, const float* __restrict__ bs) {
    int idx = blockIdx.x * blockDim.x + threadIdx.x;
    if (idx < WSTT_N) {
        int gr2 = idx / SW_;
        int k = idx - gr2 * SW_;
        int d = gr2 / G4_;
        int r = gr2 - d * G4_;
        const float* W = d ? Wih_b : Wih_f;
        g_WSTT[idx] = W[(size_t)r * (H_ + SW_) + H_ + k];
        return;
    }
    int j = idx - WSTT_N;
    if (j < WSM_N) {
        int row = j / H2P_;
        int jj = j - row * H2P_;
        int d = jj >= HP_;
        int c = jj - d * HP_;
        float v = 0.f;
        if (c < H_) {
            int col = d * H_ + c;
            const float* src; int r;
            if (row < 3)       { src = Wc; r = row; }
            else if (row < 53) { src = Ws; r = row - 3; }
            else               { src = Wd; r = row - 53; }
            v = src[(size_t)r * H2_ + col];
        }
        g_Wsm[j] = __float2half(v);
        return;
    }
    int e = j - WSM_N;
    if (e < WSMT_N) {
        int col = e / NCS_;
        int row = e - col * NCS_;
        float v = (row < 3) ? Wc[(size_t)row * H2_ + col] : Ws[(size_t)(row - 3) * H2_ + col];
        g_WsmT[(size_t)col * 56 + row] = v;
        return;
    }
    int m = e - WSMT_N;
    if (m < H2P_) {
        int d = m >= HP_;
        int i = m - d * HP_;
        g_h[0][m] = (i < H_) ? h0[d * H_ + i] : 0.f;
    } else if (m < H2P_ + SD_ * SW_) {
        g_stack[0][m - H2P_] = st0[m - H2P_];
    } else if (m < H2P_ + SD_ * SW_ + 256) {
        g_arr[m - H2P_ - SD_ * SW_] = 0u;
    } else if (m < H2P_ + SD_ * SW_ + 256 + 128) {
        int q = m - H2P_ - SD_ * SW_ - 256;      // 0..127
        int b = 1 + q / 64, r = q % 64;
        float v = (r < 3) ? bc[r] : ((r < 53) ? bs[r - 3] : 0.f);
        g_cs_buf[b][r] = v;
    } else if (m == H2P_ + SD_ * SW_ + 256 + 128) {
        g_gen = 0u;
    }
}
#define MISC_N (WSTT_N + WSM_N + WSMT_N + H2P_ + SD_ * SW_ + 256 + 129)

// ctrl/si for step 0 from h0 (full dot, off critical path)
__global__ void prep_cs0(const float* __restrict__ h0,
                         const float* __restrict__ Wc, const float* __restrict__ Ws,
                         const float* __restrict__ bc, const float* __restrict__ bs) {
    const int row = blockIdx.x;            // 0..52
    const float* Wrow = (row < 3) ? Wc + (size_t)row * H2_ : Ws + (size_t)(row - 3) * H2_;
    const float bias = (row < 3) ? bc[row] : bs[row - 3];
    __shared__ float red[256];
    float acc = 0.f;
    for (int i = threadIdx.x; i < H2_; i += 256) acc = fmaf(Wrow[i], h0[i], acc);
    red[threadIdx.x] = acc;
    __syncthreads();
    for (int s = 128; s; s >>= 1) {
        if (threadIdx.x < s) red[threadIdx.x] += red[threadIdx.x + s];
        __syncthreads();
    }
    if (threadIdx.x == 0) g_cs_buf[0][row] = red[0] + bias;
}

__global__ void conv_whh(const float* __restrict__ Wf, const float* __restrict__ Wb) {
    int idx = blockIdx.x * blockDim.x + threadIdx.x;
    if (idx >= 2 * G4_ * HP_) return;
    int d = idx / (G4_ * HP_);
    int rem = idx - d * (G4_ * HP_);
    int r = rem / HP_;
    int k = rem - r * HP_;
    const float* W = d ? Wb : Wf;
    float v = (k < H_) ? W[(size_t)r * H_ + k] : 0.f;
    g_Whh[idx] = __float2half(v);
}

__global__ void __launch_bounds__(256) prep_ev(
    const float* __restrict__ Wih_f, const float* __restrict__ Wih_b,
    const float* __restrict__ bih_f, const float* __restrict__ bhh_f,
    const float* __restrict__ bih_b, const float* __restrict__ bhh_b,
    const float* __restrict__ emb) {
    __shared__ float As[64][17];
    __shared__ float Bs[16][49];
    const int dir = blockIdx.y;
    const float* Wih = dir ? Wih_b : Wih_f;
    const float* bih = dir ? bih_b : bih_f;
    const float* bhh = dir ? bhh_b : bhh_f;
    const int r0 = blockIdx.x * 64;
    const int tid = threadIdx.x;
    const int ty = tid >> 4;
    const int tx = tid & 15;
    float acc[4][3] = {};
    for (int k0 = 0; k0 < H_; k0 += 16) {
        #pragma unroll
        for (int j = 0; j < 4; ++j) {
            int li = tid + j * 256;
            int row = li >> 4, kk = li & 15;
            int gr = r0 + row, gk = k0 + kk;
            As[row][kk] = (gr < G4_ && gk < H_) ? Wih[(size_t)gr * (H_ + SW_) + gk] : 0.f;
        }
        #pragma unroll
        for (int j = 0; j < 3; ++j) {
            int li = tid + j * 256;
            int v = li >> 4, kk = li & 15;
            int gk = k0 + kk;
            Bs[kk][v] = (v < V_ && gk < H_) ? emb[(size_t)v * H_ + gk] : 0.f;
        }
        __syncthreads();
        #pragma unroll
        for (int kk = 0; kk < 16; ++kk) {
            float a0 = As[ty * 4 + 0][kk], a1 = As[ty * 4 + 1][kk];
            float a2 = As[ty * 4 + 2][kk], a3 = As[ty * 4 + 3][kk];
            float b0 = Bs[kk][tx * 3 + 0], b1 = Bs[kk][tx * 3 + 1], b2 = Bs[kk][tx * 3 + 2];
            acc[0][0] = fmaf(a0, b0, acc[0][0]); acc[0][1] = fmaf(a0, b1, acc[0][1]); acc[0][2] = fmaf(a0, b2, acc[0][2]);
            acc[1][0] = fmaf(a1, b0, acc[1][0]); acc[1][1] = fmaf(a1, b1, acc[1][1]); acc[1][2] = fmaf(a1, b2, acc[1][2]);
            acc[2][0] = fmaf(a2, b0, acc[2][0]); acc[2][1] = fmaf(a2, b1, acc[2][1]); acc[2][2] = fmaf(a2, b2, acc[2][2]);
            acc[3][0] = fmaf(a3, b0, acc[3][0]); acc[3][1] = fmaf(a3, b1, acc[3][1]); acc[3][2] = fmaf(a3, b2, acc[3][2]);
        }
        __syncthreads();
    }
    #pragma unroll
    for (int i = 0; i < 4; ++i) {
        int r = r0 + ty * 4 + i;
        if (r >= G4_) continue;
        float bb = bih[r] + bhh[r];
        #pragma unroll
        for (int j = 0; j < 3; ++j) {
            int v = tx * 3 + j;
            if (v < V_) g_EV[((size_t)(dir * V_ + v)) * G4_ + r] = acc[i][j] + bb;
        }
    }
}

// dual-accumulator fp16x8 dot
__device__ __forceinline__ void fma8d(float& a, float& b, uint4 u, float4 hA, float4 hB) {
    float2 f0 = __half22float2(*reinterpret_cast<__half2*>(&u.x));
    float2 f1 = __half22float2(*reinterpret_cast<__half2*>(&u.y));
    float2 f2 = __half22float2(*reinterpret_cast<__half2*>(&u.z));
    float2 f3 = __half22float2(*reinterpret_cast<__half2*>(&u.w));
    a = fmaf(f0.x, hA.x, a); a = fmaf(f0.y, hA.y, a);
    a = fmaf(f1.x, hA.z, a); a = fmaf(f1.y, hA.w, a);
    b = fmaf(f2.x, hB.x, b); b = fmaf(f2.y, hB.y, b);
    b = fmaf(f3.x, hB.z, b); b = fmaf(f3.y, hB.w, b);
}

// NR rows, single k-pass, all LDGs in flight per iteration
template<int NR>
__device__ __forceinline__ void row_dots(const uint4* const* wp, const float4* hb,
                                         int lane, float* accOut) {
    float aA[NR], aB[NR];
    #pragma unroll
    for (int r = 0; r < NR; ++r) { aA[r] = 0.f; aB[r] = 0.f; }
    #pragma unroll
    for (int it = 0; it < 6; ++it) {
        const int o = it * 32 + lane;
        const float4 hA = hb[2 * o];
        const float4 hB = hb[2 * o + 1];
        #pragma unroll
        for (int r = 0; r < NR; ++r) {
            uint4 u = wp[r][o];
            fma8d(aA[r], aB[r], u, hA, hB);
        }
    }
    #pragma unroll
    for (int r = 0; r < NR; ++r) accOut[r] = aA[r] + aB[r];
}

// full-length (2H) small-row dot over sh_h (dec rows)
__device__ __forceinline__ float small_dot(int sid, const float* sh_h, int lane) {
    const uint4* W = (const uint4*)(g_Wsm + (size_t)sid * H2P_);
    const float4* s4 = (const float4*)sh_h;
    float a = 0.f, b = 0.f;
    #pragma unroll
    for (int it = 0; it < 12; ++it) {
        const int o = lane + it * 32;
        uint4 u = W[o];
        fma8d(a, b, u, s4[2 * o], s4[2 * o + 1]);
    }
    float acc = a + b;
    #pragma unroll
    for (int o = 16; o; o >>= 1) acc += __shfl_xor_sync(0xffffffffu, acc, o);
    return acc;
}

// ---------------- persistent main kernel: ONE rendezvous per step ----------------
__global__ void __launch_bounds__(TPB_, 1) rnn_main(
    const int* __restrict__ tokens, const float* __restrict__ cell0,
    const float* __restrict__ bctrl, const float* __restrict__ bsi,
    const float* __restrict__ bdec,
    float* __restrict__ out, int T) {
    __shared__ __align__(16) float sh_h[H2P_];
    __shared__ float s_gate[80];
    __shared__ float s_stop[64];   // padded; [50..63] zeroed
    __shared__ float s_hnew[32];

    const int bid  = blockIdx.x;
    const int tid  = threadIdx.x;
    const int lane = tid & 31;
    const int warp = tid >> 5;
    const int NB   = gridDim.x;
    const int hub  = NB - 1;

    // block-owned contiguous unit range
    const int ubase = H2_ / NB, urem = H2_ % NB;
    const int un = ubase + (bid < urem ? 1 : 0);
    const int u0 = bid * ubase + (bid < urem ? bid : urem);
    const int nrows = 4 * un;
    const bool has_dec = (bid >= NCS_ && bid < NSMALL_);
    const int dstride = has_dec ? (NWARP_ - 1) : NWARP_;
    const bool is_decw = (has_dec && warp == NWARP_ - 1);

    // ---- static per-warp row list (fixed across steps), max 4 rows ----
    int nr = 0;
    int rowrl[4], rowd[4], rowg[4];
    const uint4* wp[4];
    if (!is_decw) {
        for (int rl = warp; rl < nrows && nr < 4; rl += dstride) {
            const int ul = rl >> 2, g = rl & 3;
            const int uu = u0 + ul;
            const int d = (uu >= H_);
            const int i = uu - d * H_;
            const int grow = g * H_ + i;
            rowrl[nr] = rl; rowd[nr] = d; rowg[nr] = grow;
            wp[nr] = (const uint4*)(g_Whh + ((size_t)(d * G4_ + grow)) * HP_);
            ++nr;
        }
    }
    bool dirsame = true;
    for (int ri = 1; ri < nr; ++ri) if (rowd[ri] != rowd[0]) dirsame = false;

    // persistent cell state + hoisted static stack-projection weights
    float creg0 = 0.f;
    float wreg[7];
    int myu0 = -1;
    if (warp < un) {
        myu0 = u0 + warp;
        creg0 = cell0[myu0];
        const int d = (myu0 >= H_);
        const int i = myu0 - d * H_;
        const int g8 = lane >> 3, k0 = lane & 7;
        const float* wst = g_WSTT + ((size_t)(d * G4_ + g8 * H_ + i)) * SW_;
        #pragma unroll
        for (int j = 0; j < 7; ++j) {
            const int k = k0 + 8 * j;
            wreg[j] = (k < SW_) ? wst[k] : 0.f;
        }
    }
    if (tid >= SW_ && tid < 64) s_stop[tid] = 0.f;     // pad zero (never rewritten)

    unsigned gen = 0;

    for (int t = 0; t <= T; ++t) {
        // ---- stage h(t) ----
        __syncthreads();
        ((float4*)sh_h)[tid] = __ldcg((const float4*)g_h[t & 1] + tid);   // H2P_/4 == TPB_
        __syncthreads();

        if (t == T) {   // final logits row for step T-1
            if (is_decw) {
                float acc = small_dot(bid, sh_h, lane);
                if (lane == 0) out[(size_t)(T - 1) * V_ + (bid - NCS_)] = acc + bdec[bid - NCS_];
            }
            break;
        }
        const int tok = tokens[t];

        // ---- hub: bias-init the t+2 ctrl/si accumulator ----
        if (bid == hub && tid < NCS_)
            g_cs_buf[(t + 2) % 3][tid] = (tid < 3) ? bctrl[tid] : bsi[tid - 3];

        // ---- s_stop + stack rows (ctrl/si already complete in buf[t%3]) ----
        const float* stOld = g_stack[t & 1];
        float* stNew = g_stack[(t + 1) & 1];
        if (tid < SW_ + 450) {
            const float* cb = g_cs_buf[t % 3];
            const float c0r = __ldcg(&cb[0]);
            const float c1r = __ldcg(&cb[1]);
            const float c2r = __ldcg(&cb[2]);
            const float m = fmaxf(c0r, fmaxf(c1r, c2r));
            const float e0 = __expf(c0r - m), e1 = __expf(c1r - m), e2 = __expf(c2r - m);
            const float inv = 1.f / (e0 + e1 + e2);
            const float c0 = e0 * inv, c1 = e1 * inv, c2 = e2 * inv;
            if (tid < SW_) {
                const float sv = tanhf(__ldcg(&cb[3 + tid]));
                const float sp = c2 * __ldcg(&stOld[tid]) + c0 * sv + c1 * __ldcg(&stOld[SW_ + tid]);
                s_stop[tid] = sp;
                if (bid == hub) stNew[tid] = sp;
            } else if (bid == hub) {
                const int idx = tid - SW_;
                const int dd = 1 + idx / SW_;
                const int k = idx - (dd - 1) * SW_;
                const float sv = tanhf(__ldcg(&cb[3 + k]));   // unused for dd>=1 'up' except dd==0
                (void)sv;
                const float up = __ldcg(&stOld[(dd - 1) * SW_ + k]);
                const float dn = (dd < SD_ - 1) ? __ldcg(&stOld[(dd + 1) * SW_ + k]) : 0.f;
                stNew[dd * SW_ + k] = c2 * __ldcg(&stOld[dd * SW_ + k]) + c0 * up + c1 * dn;
            }
        }

        // ---- big gate-row dots ----
        if (!is_decw && nr > 0) {
            float acc[4] = {0.f, 0.f, 0.f, 0.f};
            if (dirsame) {
                const float4* hb = (const float4*)(sh_h + rowd[0] * HP_);
                switch (nr) {
                    case 4: row_dots<4>(wp, hb, lane, acc); break;
                    case 3: row_dots<3>(wp, hb, lane, acc); break;
                    case 2: row_dots<2>(wp, hb, lane, acc); break;
                    default: row_dots<1>(wp, hb, lane, acc); break;
                }
            } else {
                for (int ri = 0; ri < nr; ++ri) {
                    const float4* hb = (const float4*)(sh_h + rowd[ri] * HP_);
                    row_dots<1>(wp + ri, hb, lane, acc + ri);
                }
            }
            #pragma unroll
            for (int ri = 0; ri < 4; ++ri) {
                if (ri < nr) {
                    float a = acc[ri];
                    #pragma unroll
                    for (int o = 16; o; o >>= 1) a += __shfl_xor_sync(0xffffffffu, a, o);
                    if (lane == 0) {
                        const float ev = __ldg(&g_EV[((size_t)(rowd[ri] * V_ + tok)) * G4_ + rowg[ri]]);
                        s_gate[rowrl[ri]] = a + ev;
                    }
                }
            }
        }

        __syncthreads();   // s_gate + s_stop ready

        // ---- pointwise LSTM update (warp per owned unit) ----
        if (myu0 >= 0) {
            const int u = myu0;
            const int ul = u - u0;
            const int d = (u >= H_);
            const int i = u - d * H_;
            const int g8 = lane >> 3;
            const int k0 = lane & 7;
            float sp = 0.f;
            #pragma unroll
            for (int j = 0; j < 7; ++j) sp = fmaf(wreg[j], s_stop[k0 + 8 * j], sp);
            sp += __shfl_xor_sync(0xffffffffu, sp, 1);
            sp += __shfl_xor_sync(0xffffffffu, sp, 2);
            sp += __shfl_xor_sync(0xffffffffu, sp, 4);
            const float tot = s_gate[4 * ul + g8] + sp;
            const float act = (g8 == 2) ? tanhf(tot) : (1.f / (1.f + __expf(-tot)));
            const float is = __shfl_sync(0xffffffffu, act, 0);
            const float fs = __shfl_sync(0xffffffffu, act, 8);
            const float gt = __shfl_sync(0xffffffffu, act, 16);
            const float os = __shfl_sync(0xffffffffu, act, 24);
            if (lane == 0) {
                const float cc = fs * creg0 + is * gt;
                creg0 = cc;
                const float hn = os * tanhf(cc);
                g_h[(t + 1) & 1][d * HP_ + i] = hn;
                s_hnew[warp] = hn;
            }
        }
        __syncthreads();   // s_hnew ready

        // ---- distributed ctrl/si partials for step t+1 ----
        if (tid < NCS_) {
            float acc = 0.f;
            for (int j = 0; j < un; ++j)
                acc = fmaf(__ldg(&g_WsmT[(size_t)(u0 + j) * 56 + tid]), s_hnew[j], acc);
            atomicAdd(&g_cs_buf[(t + 1) % 3][tid], acc);
        }

        // ---- barrier arrive ----
        __syncthreads();
        if (tid == 0) { __threadfence(); g_arr[bid] = ++gen; }
        else ++gen;

        // ---- dec logits overlapped with barrier wait (sh_h still = h(t)) ----
        if (is_decw && t >= 1) {
            float acc = small_dot(bid, sh_h, lane);
            if (lane == 0) out[(size_t)(t - 1) * V_ + (bid - NCS_)] = acc + bdec[bid - NCS_];
        }

        // ---- barrier release ----
        if (bid == hub) {
            if (tid < NB) { while (g_arr[tid] < gen) { __nanosleep(16); } }
            __syncthreads();
            if (tid == 0) g_gen = gen;
        } else {
            if (tid == 0) { while (g_gen < gen) { __nanosleep(16); } }
        }
        __syncthreads();
    }
}

// ---------------- launch ----------------
extern "C" void kernel_launch(void* const* d_in, const int* in_sizes, int n_in,
                              void* d_out, int out_size) {
    const int*   tokens  = (const int*)  d_in[0];
    const float* hidden0 = (const float*)d_in[1];
    const float* cell0   = (const float*)d_in[2];
    const float* stack0  = (const float*)d_in[3];
    const float* emb     = (const float*)d_in[4];
    const float* Wctrl   = (const float*)d_in[5];
    const float* bctrl   = (const float*)d_in[6];
    const float* Wsi     = (const float*)d_in[7];
    const float* bsi     = (const float*)d_in[8];
    const float* Wih_f   = (const float*)d_in[9];
    const float* Whh_f   = (const float*)d_in[10];
    const float* bih_f   = (const float*)d_in[11];
    const float* bhh_f   = (const float*)d_in[12];
    const float* Wih_b   = (const float*)d_in[13];
    const float* Whh_b   = (const float*)d_in[14];
    const float* bih_b   = (const float*)d_in[15];
    const float* bhh_b   = (const float*)d_in[16];
    const float* Wdec    = (const float*)d_in[17];
    const float* bdec    = (const float*)d_in[18];
    float* out = (float*)d_out;
    const int T = in_sizes[0];

    int dev = 0;
    cudaGetDevice(&dev);
    int nsm = 0;
    cudaDeviceGetAttribute(&nsm, cudaDevAttrMultiProcessorCount, dev);
    if (nsm <= 0) nsm = 148;
    if (nsm > 256) nsm = 256;

    prep_misc<<<(MISC_N + 255) / 256, 256>>>(hidden0, stack0, Wih_f, Wih_b,
                                             Wctrl, Wsi, Wdec, bctrl, bsi);
    prep_cs0<<<NCS_, 256>>>(hidden0, Wctrl, Wsi, bctrl, bsi);
    conv_whh<<<(2 * G4_ * HP_ + 255) / 256, 256>>>(Whh_f, Whh_b);
    dim3 gev((G4_ + 63) / 64, 2);
    prep_ev<<<gev, 256>>>(Wih_f, Wih_b, bih_f, bhh_f, bih_b, bhh_b, emb);
    rnn_main<<<nsm, TPB_>>>(tokens, cell0, bctrl, bsi, bdec, out, T);
}